// round 5
// baseline (speedup 1.0000x reference)
#include <cuda_runtime.h>
#include <cuda_fp16.h>
#include <cstdint>
#include <math.h>

// ---------------- problem constants ----------------
#define NUM_E 1024
#define DIM   64
#define TT    2048
#define BB    32
#define NROWS (BB * TT)          // 65536
#define NELEM (BB * DIM * TT)    // 4194304

// output layout (flattened tuple, fp32)
#define COMMIT_OFF 4194304
#define PERP_OFF   4194305
#define AVG_OFF    4194306
#define IDX_OFF    4195330
#define USAGE_OFF  4260866

// ---------------- tiling ----------------
#define ROWS_CTA 128                 // rows per CTA (8 m-tiles)
#define NCH      8                   // code chunks of 128
#define CHB      16384               // packed B chunk: 4 pkt * 16 nt * 32 * 8B
#define CAP      4096                // candidate buffer entries

// smem offsets
#define SA_OFF    0                  // A frags: 8 mt * 4 pkt * 32 * 16B = 16KB
#define SB_OFF    16384              // B frags: 2 * 16KB
#define SX_OFF    49152              // x fp32: 128*64*4 = 32KB
#define SE2_OFF   81920              // 4KB
#define SW_OFF    86016              // per-row window W: 128*4
#define SRED_OFF  86528              // chunk row-min: 128*4 floats
#define SSLOT_OFF 88576              // per-row result u64: 128*8 (8-aligned)
#define SBUF_OFF  89600              // candidates u32: 4096*4 = 16KB
#define SCNT_OFF  105984
#define SMEM_DYN  106240

// ---------------- device scratch ----------------
__device__ __align__(16) unsigned char g_Bp[NCH * CHB];  // packed B frags (split 0)
__device__ float g_e2[NUM_E];
__device__ float g_emax2[8];
__device__ float g_demax2[8];
__device__ int   g_idx[NROWS];
__device__ int   g_counts[NUM_E];
__device__ float g_sumsq;

// ---------------- helpers ----------------
__device__ __forceinline__ uint32_t smem_u32(const void* p) {
    uint32_t a;
    asm("{ .reg .u64 t; cvta.to.shared.u64 t, %1; cvt.u32.u64 %0, t; }" : "=r"(a) : "l"(p));
    return a;
}
__device__ __forceinline__ void cp16(uint32_t saddr, const void* g) {
    asm volatile("cp.async.cg.shared.global [%0], [%1], 16;" :: "r"(saddr), "l"(g));
}
__device__ __forceinline__ void cp_commit() {
    asm volatile("cp.async.commit_group;" ::: "memory");
}
__device__ __forceinline__ void mma16816(float* d, const uint4 a, const uint2 b) {
    asm volatile(
        "mma.sync.aligned.m16n8k16.row.col.f32.f16.f16.f32 "
        "{%0,%1,%2,%3}, {%4,%5,%6,%7}, {%8,%9}, {%0,%1,%2,%3};"
        : "+f"(d[0]), "+f"(d[1]), "+f"(d[2]), "+f"(d[3])
        : "r"(a.x), "r"(a.y), "r"(a.z), "r"(a.w), "r"(b.x), "r"(b.y));
}
__device__ __forceinline__ uint32_t okey(float f) {   // order-preserving fp32 -> u32
    uint32_t b = __float_as_uint(f);
    return (b & 0x80000000u) ? ~b : (b | 0x80000000u);
}

// ---------------- prep: pack fp16 codebook frags + norms + error maxima ----------------
__global__ void prep_kernel(const float* __restrict__ embed) {
    __shared__ float smax1[128], smax2[128];
    const int c = blockIdx.x * 128 + threadIdx.x;
    const float* e = embed + (size_t)c * DIM;
    uint32_t h0[32];
    double e2d = 0.0;
    float de2 = 0.f;
#pragma unroll 8
    for (int j = 0; j < 32; ++j) {
        float2 v = *(const float2*)(e + 2 * j);
        e2d += (double)v.x * v.x + (double)v.y * v.y;
        __half a = __float2half_rn(v.x), b = __float2half_rn(v.y);
        float dx = v.x - __half2float(a), dy = v.y - __half2float(b);
        de2 += dx * dx + dy * dy;
        h0[j] = (uint32_t)__half_as_ushort(a) | ((uint32_t)__half_as_ushort(b) << 16);
    }
    const float e2f = (float)e2d;
    g_e2[c] = e2f;
    g_counts[c] = 0;
    if (c == 0) g_sumsq = 0.f;

    const int chunk = c >> 7, n_in = c & 127, nt = n_in >> 3, lq = n_in & 7;
    uint32_t* dstb = (uint32_t*)(g_Bp + (size_t)chunk * CHB);
#pragma unroll
    for (int pkt = 0; pkt < 4; ++pkt) {
        const int kb = pkt * 8;
#pragma unroll
        for (int cc = 0; cc < 4; ++cc) {
            uint32_t* d = dstb + (((pkt * 16 + nt) * 32) + 4 * lq + cc) * 2;
            d[0] = h0[kb + cc];
            d[1] = h0[kb + 4 + cc];
        }
    }
    // block max of ||e||^2 and ||de||^2
    smax1[threadIdx.x] = e2f;
    smax2[threadIdx.x] = de2;
    __syncthreads();
    for (int s = 64; s; s >>= 1) {
        if (threadIdx.x < s) {
            smax1[threadIdx.x] = fmaxf(smax1[threadIdx.x], smax1[threadIdx.x + s]);
            smax2[threadIdx.x] = fmaxf(smax2[threadIdx.x], smax2[threadIdx.x + s]);
        }
        __syncthreads();
    }
    if (threadIdx.x == 0) {
        g_emax2[blockIdx.x] = smax1[0];
        g_demax2[blockIdx.x] = smax2[0];
    }
}

// ---------------- main: approx HMMA GEMM + windowed exact fp64 rescore ----------------
__global__ void __launch_bounds__(512, 1)
vq_mma_kernel(const float* __restrict__ x, const float* __restrict__ embed,
              float* __restrict__ out_idxf) {
    extern __shared__ char sm[];
    uint32_t* sA   = (uint32_t*)(sm + SA_OFF);
    float*    sX   = (float*)(sm + SX_OFF);
    float*    sE2  = (float*)(sm + SE2_OFF);
    float*    sW   = (float*)(sm + SW_OFF);
    float*    sRed = (float*)(sm + SRED_OFF);
    unsigned long long* sSlot = (unsigned long long*)(sm + SSLOT_OFF);
    uint32_t* sBuf = (uint32_t*)(sm + SBUF_OFF);
    int*      sCnt = (int*)(sm + SCNT_OFF);
    const uint32_t sBaddr = smem_u32(sm + SB_OFF);

    const int tid = threadIdx.x, lane = tid & 31, w = tid >> 5;
    const int rg = w & 3, cg = w >> 2;   // 4 row-groups x 4 code-groups

    // prefetch B chunks 0,1
    {
        const char* src0 = (const char*)g_Bp;
        for (int k = tid; k < CHB / 16; k += 512) cp16(sBaddr + k * 16, src0 + k * 16);
        cp_commit();
        const char* src1 = (const char*)g_Bp + CHB;
        for (int k = tid; k < CHB / 16; k += 512) cp16(sBaddr + CHB + k * 16, src1 + k * 16);
        cp_commit();
    }

    if (tid < ROWS_CTA) sSlot[tid] = 0xFFFFFFFFFFFFFFFFull;
    if (tid == 0) *sCnt = 0;

    // error maxima
    float em2 = g_emax2[0], dm2 = g_demax2[0];
#pragma unroll
    for (int i = 1; i < 8; ++i) {
        em2 = fmaxf(em2, g_emax2[i]);
        dm2 = fmaxf(dm2, g_demax2[i]);
    }
    const float EM = sqrtf(em2), dEM = sqrtf(dm2);

    // build A fragments + fp32 x tile; thread = (row, quarter)
    {
        const int r = tid >> 2, q = tid & 3;
        const int grow = blockIdx.x * ROWS_CTA + r;
        const float* xp = x + (size_t)(grow >> 11) * (DIM * TT) + (grow & (TT - 1));
        uint32_t h0[8];
        float x2 = 0.f;
#pragma unroll
        for (int j = 0; j < 8; ++j) {
            float va = xp[(size_t)(16 * q + 2 * j) * TT];
            float vb = xp[(size_t)(16 * q + 2 * j + 1) * TT];
            sX[r * 64 + 16 * q + 2 * j] = va;
            sX[r * 64 + 16 * q + 2 * j + 1] = vb;
            x2 += va * va + vb * vb;
            h0[j] = (uint32_t)__half_as_ushort(__float2half_rn(va)) |
                    ((uint32_t)__half_as_ushort(__float2half_rn(vb)) << 16);
        }
        // quad reduce x2 (q = 0..3 are lane quad)
        x2 += __shfl_xor_sync(0xffffffffu, x2, 1);
        x2 += __shfl_xor_sync(0xffffffffu, x2, 2);
        if (q == 0) {
            const float xn = sqrtf(x2);
            sW[r] = 4.0f * (4.8828125e-4f * xn * EM + 1.001f * xn * dEM) + 0.02f;
        }
        const int mt = r >> 4, rr = r & 15;
        const int wsel = (rr < 8) ? 0 : 1;
#pragma unroll
        for (int c = 0; c < 4; ++c) {
            uint32_t* dst = sA + (((mt * 4 + q) * 32) + 4 * (rr & 7) + c) * 4 + wsel;
            dst[0] = h0[c];
            dst[2] = h0[4 + c];
        }
        for (int i = tid; i < NUM_E; i += 512) sE2[i] = g_e2[i];
    }
    __syncthreads();

    // per-lane row bases and windows (4 row-positions: h = 2m+hb)
    const int q4 = lane >> 2;
    int rowh[4];
    float wrow[4], Th[4];
#pragma unroll
    for (int h = 0; h < 4; ++h) {
        const int m = h >> 1, hb = h & 1;
        rowh[h] = rg * 32 + m * 16 + hb * 8 + q4;
        wrow[h] = sW[rowh[h]];
        Th[h] = 3.4e38f;
    }

    for (int ch = 0; ch < NCH; ++ch) {
        if (ch < NCH - 1) asm volatile("cp.async.wait_group 1;" ::: "memory");
        else              asm volatile("cp.async.wait_group 0;" ::: "memory");
        __syncthreads();
        const uint32_t* Bb = (const uint32_t*)(sm + SB_OFF + (ch & 1) * CHB);

        float acc[2][4][4];
#pragma unroll
        for (int m = 0; m < 2; ++m)
#pragma unroll
            for (int n = 0; n < 4; ++n)
#pragma unroll
                for (int j = 0; j < 4; ++j) acc[m][n][j] = 0.f;

#pragma unroll
        for (int kt = 0; kt < 4; ++kt) {
            uint4 Af[2];
#pragma unroll
            for (int m = 0; m < 2; ++m)
                Af[m] = *(const uint4*)(sA + ((((rg * 2 + m) * 4 + kt) * 32) + lane) * 4);
#pragma unroll
            for (int n = 0; n < 4; ++n) {
                uint2 Bf = *(const uint2*)(Bb + (((kt * 16 + cg * 4 + n) * 32) + lane) * 2);
#pragma unroll
                for (int m = 0; m < 2; ++m) mma16816(acc[m][n], Af[m], Bf);
            }
        }

        // scores in-place: s = -2*dot + e2; lane-local min per row-position
        const int cb = ch * 128 + cg * 32 + 2 * (lane & 3);
        float lmin[4] = {3.4e38f, 3.4e38f, 3.4e38f, 3.4e38f};
#pragma unroll
        for (int n = 0; n < 4; ++n) {
            const int c0 = cb + n * 8;
            const float ea = sE2[c0], eb = sE2[c0 + 1];
#pragma unroll
            for (int m = 0; m < 2; ++m) {
                acc[m][n][0] = fmaf(-2.f, acc[m][n][0], ea);
                acc[m][n][1] = fmaf(-2.f, acc[m][n][1], eb);
                acc[m][n][2] = fmaf(-2.f, acc[m][n][2], ea);
                acc[m][n][3] = fmaf(-2.f, acc[m][n][3], eb);
                lmin[2 * m]     = fminf(lmin[2 * m],     fminf(acc[m][n][0], acc[m][n][1]));
                lmin[2 * m + 1] = fminf(lmin[2 * m + 1], fminf(acc[m][n][2], acc[m][n][3]));
            }
        }
        // quad reduce mins (lanes sharing rows)
#pragma unroll
        for (int h = 0; h < 4; ++h) {
            lmin[h] = fminf(lmin[h], __shfl_xor_sync(0xffffffffu, lmin[h], 1));
            lmin[h] = fminf(lmin[h], __shfl_xor_sync(0xffffffffu, lmin[h], 2));
        }
        if ((lane & 3) == 0) {
#pragma unroll
            for (int h = 0; h < 4; ++h) sRed[rowh[h] * 4 + cg] = lmin[h];
        }
        __syncthreads();   // sRed ready; B buffer fully consumed

        if (ch + 2 < NCH) {
            const char* src = (const char*)g_Bp + (size_t)(ch + 2) * CHB;
            const uint32_t dst = sBaddr + (ch & 1) * CHB;
            for (int k = tid; k < CHB / 16; k += 512) cp16(dst + k * 16, src + k * 16);
            cp_commit();
        }

        // update running row-min T, admit candidates
#pragma unroll
        for (int h = 0; h < 4; ++h) {
            const float* rp = &sRed[rowh[h] * 4];
            float cm = fminf(fminf(rp[0], rp[1]), fminf(rp[2], rp[3]));
            Th[h] = fminf(Th[h], cm);
        }
#pragma unroll
        for (int n = 0; n < 4; ++n) {
            const int c0 = cb + n * 8;
#pragma unroll
            for (int m = 0; m < 2; ++m) {
#pragma unroll
                for (int j = 0; j < 4; ++j) {
                    const int h = 2 * m + (j >> 1);
                    const float s = acc[m][n][j];
                    if (s < Th[h] + wrow[h]) {
                        int pos = atomicAdd(sCnt, 1);
                        if (pos < CAP)
                            sBuf[pos] = ((uint32_t)rowh[h] << 10) | (uint32_t)(c0 + (j & 1));
                    }
                }
            }
        }
    }
    __syncthreads();

    // ---- exact fp64 rescore of candidates: 4 candidates per warp, 8 lanes each ----
    {
        const int C = min(*sCnt, CAP);
        const int sub = lane >> 3, sl = lane & 7;
        for (int base = w * 4; base < C; base += 16 * 4) {
            const int i = base + sub;
            double p = 0.0;
            uint32_t ent = 0;
            if (i < C) {
                ent = sBuf[i];
                const int row = ent >> 10, cidx = ent & 1023;
                const float* ep = embed + (size_t)cidx * DIM + sl * 8;
                const float* xp = sX + row * 64 + sl * 8;
#pragma unroll
                for (int j = 0; j < 4; ++j) {
                    float2 ev = *(const float2*)(ep + 2 * j);
                    float2 xv = *(const float2*)(xp + 2 * j);
                    p += (double)ev.x * ((double)ev.x - 2.0 * (double)xv.x);
                    p += (double)ev.y * ((double)ev.y - 2.0 * (double)xv.y);
                }
            }
            p += __shfl_down_sync(0xffffffffu, p, 4);
            p += __shfl_down_sync(0xffffffffu, p, 2);
            p += __shfl_down_sync(0xffffffffu, p, 1);
            if (sl == 0 && i < C) {
                const int row = ent >> 10, cidx = ent & 1023;
                unsigned long long key =
                    ((unsigned long long)okey((float)p) << 10) | (unsigned long long)cidx;
                atomicMin(&sSlot[row], key);
            }
        }
    }
    __syncthreads();

    if (tid < ROWS_CTA) {
        const int bi = (int)(sSlot[tid] & 1023ull);
        const int grow = blockIdx.x * ROWS_CTA + tid;
        g_idx[grow] = bi;
        out_idxf[grow] = (float)bi;
        atomicAdd(&g_counts[bi], 1);
    }
}

// ---------------- gather + straight-through + commitment loss ----------------
__global__ void gather_kernel(const float* __restrict__ x,
                              const float* __restrict__ embed,
                              float* __restrict__ out_q) {
    __shared__ float warpsum[8];
    const int gid = blockIdx.x * blockDim.x + threadIdx.x;
    const int lin = gid * 4;
    const int t_i = lin & (TT - 1);
    const int d_i = (lin >> 11) & (DIM - 1);
    const int b_i = lin >> 17;

    float4 xv = *(const float4*)(x + lin);
    const int rowbase = (b_i << 11) + t_i;
    int4 id = *(const int4*)(g_idx + rowbase);

    float q0 = embed[id.x * DIM + d_i];
    float q1 = embed[id.y * DIM + d_i];
    float q2 = embed[id.z * DIM + d_i];
    float q3 = embed[id.w * DIM + d_i];

    float d0 = q0 - xv.x, d1 = q1 - xv.y, d2 = q2 - xv.z, d3 = q3 - xv.w;
    float4 ov = make_float4(xv.x + d0, xv.y + d1, xv.z + d2, xv.w + d3);
    *(float4*)(out_q + lin) = ov;

    float s = d0 * d0 + d1 * d1 + d2 * d2 + d3 * d3;
#pragma unroll
    for (int o = 16; o; o >>= 1) s += __shfl_down_sync(0xffffffffu, s, o);
    const int lane = threadIdx.x & 31, w = threadIdx.x >> 5;
    if (lane == 0) warpsum[w] = s;
    __syncthreads();
    if (w == 0) {
        float v = lane < 8 ? warpsum[lane] : 0.f;
#pragma unroll
        for (int o = 4; o; o >>= 1) v += __shfl_down_sync(0xffffffffu, v, o);
        if (lane == 0) atomicAdd(&g_sumsq, v);
    }
}

// ---------------- finalize ----------------
__global__ void finalize_kernel(float* __restrict__ out) {
    __shared__ float s1[32], s2[32];
    const int tid = threadIdx.x;
    float p = (float)g_counts[tid] * (1.0f / (float)NROWS);
    out[AVG_OFF + tid] = p;
    float t1 = p * logf(p + 1e-10f);
    float t2 = p * logf(p * (float)NUM_E + 1e-10f);
#pragma unroll
    for (int o = 16; o; o >>= 1) {
        t1 += __shfl_down_sync(0xffffffffu, t1, o);
        t2 += __shfl_down_sync(0xffffffffu, t2, o);
    }
    const int lane = tid & 31, w = tid >> 5;
    if (lane == 0) { s1[w] = t1; s2[w] = t2; }
    __syncthreads();
    if (w == 0) {
        float a = s1[lane], b = s2[lane];
#pragma unroll
        for (int o = 16; o; o >>= 1) {
            a += __shfl_down_sync(0xffffffffu, a, o);
            b += __shfl_down_sync(0xffffffffu, b, o);
        }
        if (lane == 0) {
            out[PERP_OFF]   = expf(-a);
            out[USAGE_OFF]  = b;
            out[COMMIT_OFF] = 0.25f * g_sumsq / (float)NELEM;
        }
    }
}

extern "C" void kernel_launch(void* const* d_in, const int* in_sizes, int n_in,
                              void* d_out, int out_size) {
    const float* x     = (const float*)d_in[0];
    const float* embed = (const float*)d_in[1];
    float* out = (float*)d_out;

    cudaFuncSetAttribute(vq_mma_kernel, cudaFuncAttributeMaxDynamicSharedMemorySize, SMEM_DYN);

    prep_kernel<<<8, 128>>>(embed);
    vq_mma_kernel<<<NROWS / ROWS_CTA, 512, SMEM_DYN>>>(x, embed, out + IDX_OFF);
    gather_kernel<<<NELEM / (256 * 4), 256>>>(x, embed, out);
    finalize_kernel<<<1, 1024>>>(out);
}

// round 6
// speedup vs baseline: 1.6247x; 1.6247x over previous
#include <cuda_runtime.h>
#include <cuda_fp16.h>
#include <cstdint>
#include <math.h>

// ---------------- problem constants ----------------
#define NUM_E 1024
#define DIM   64
#define TT    2048
#define BB    32
#define NROWS (BB * TT)          // 65536
#define NELEM (BB * DIM * TT)    // 4194304

// output layout (flattened tuple, fp32)
#define COMMIT_OFF 4194304
#define PERP_OFF   4194305
#define AVG_OFF    4194306
#define IDX_OFF    4195330
#define USAGE_OFF  4260866

// ---------------- tiling ----------------
#define ROWS_CTA 128                 // rows per CTA (8 m-tiles)
#define NRB      (NROWS / ROWS_CTA)  // 512 row-blocks
#define NCH      8                   // total code chunks of 128
#define CPC      4                   // chunks per CTA (codes split x2)
#define CHB      32768               // packed B chunk: 8 pkt * 16 nt * 32 * 8B

// smem offsets
#define SA_OFF   0                   // A frags: 8 mt * 8 pkt * 32 * 16B = 32KB
#define SB_OFF   32768               // B frags: 2 * 32KB
#define SE2_OFF  98304               // 4KB
#define SRF_OFF  102400              // 128*4 floats
#define SRI_OFF  104448              // 128*4 ints
#define SX_OFF   106496              // x fp32 tile: 128*64*4 = 32KB
#define SMEM_DYN 139264

#define INV2048 4.8828125e-4f

// ---------------- device scratch ----------------
__device__ __align__(16) unsigned char g_Bp[NCH * CHB];  // packed B frags
__device__ float g_e2[NUM_E];
__device__ unsigned long long g_slot[NROWS];   // packed (okey(score)<<10 | idx)
__device__ int   g_done[NRB];
__device__ int   g_counts[NUM_E];
__device__ float g_sumsq;

// ---------------- helpers ----------------
__device__ __forceinline__ uint32_t smem_u32(const void* p) {
    uint32_t a;
    asm("{ .reg .u64 t; cvta.to.shared.u64 t, %1; cvt.u32.u64 %0, t; }" : "=r"(a) : "l"(p));
    return a;
}
__device__ __forceinline__ void cp16(uint32_t saddr, const void* g) {
    asm volatile("cp.async.cg.shared.global [%0], [%1], 16;" :: "r"(saddr), "l"(g));
}
__device__ __forceinline__ void cp_commit() {
    asm volatile("cp.async.commit_group;" ::: "memory");
}
__device__ __forceinline__ void mma16816(float* d, const uint4 a, const uint2 b) {
    asm volatile(
        "mma.sync.aligned.m16n8k16.row.col.f32.f16.f16.f32 "
        "{%0,%1,%2,%3}, {%4,%5,%6,%7}, {%8,%9}, {%0,%1,%2,%3};"
        : "+f"(d[0]), "+f"(d[1]), "+f"(d[2]), "+f"(d[3])
        : "r"(a.x), "r"(a.y), "r"(a.z), "r"(a.w), "r"(b.x), "r"(b.y));
}
// scaled 2-split: v = h0 + h1/2048 with error ~2^-33
__device__ __forceinline__ void split2(float v, uint32_t& u0, uint32_t& u1) {
    __half h0 = __float2half_rn(v);
    float f0 = __half2float(h0);
    __half h1 = __float2half_rn((v - f0) * 2048.0f);
    u0 = (uint32_t)__half_as_ushort(h0);
    u1 = (uint32_t)__half_as_ushort(h1);
}
__device__ __forceinline__ uint32_t okey(float f) {   // order-preserving fp32 -> u32
    uint32_t b = __float_as_uint(f);
    return (b & 0x80000000u) ? ~b : (b | 0x80000000u);
}

// ---------------- prep: pack codebook frags + norms + zero scratch ----------------
// 8 blocks x 128 threads, one code per thread
__global__ void prep_kernel(const float* __restrict__ embed) {
    const int c = blockIdx.x * 128 + threadIdx.x;
    const float* e = embed + (size_t)c * DIM;
    uint32_t h0[32], h1[32];
    float s = 0.f;
#pragma unroll 8
    for (int j = 0; j < 32; ++j) {
        float2 v = *(const float2*)(e + 2 * j);
        s += v.x * v.x + v.y * v.y;
        uint32_t a0, a1, b0, b1;
        split2(v.x, a0, a1);
        split2(v.y, b0, b1);
        h0[j] = a0 | (b0 << 16);
        h1[j] = a1 | (b1 << 16);
    }
    g_e2[c] = s;
    g_counts[c] = 0;
    if (c == 0) g_sumsq = 0.f;
    if (c < NRB) g_done[c] = 0;
    for (int i = c; i < NROWS; i += 1024) g_slot[i] = 0xFFFFFFFFFFFFFFFFull;

    const int chunk = c >> 7, n_in = c & 127, nt = n_in >> 3, lq = n_in & 7;
    uint32_t* dstb = (uint32_t*)(g_Bp + (size_t)chunk * CHB);
#pragma unroll
    for (int pkt = 0; pkt < 8; ++pkt) {
        const uint32_t* hp = (pkt < 4) ? h0 : h1;
        const int kb = (pkt & 3) * 8;
#pragma unroll
        for (int cc = 0; cc < 4; ++cc) {
            uint32_t* d = dstb + (((pkt * 16 + nt) * 32) + 4 * lq + cc) * 2;
            d[0] = hp[kb + cc];
            d[1] = hp[kb + 4 + cc];
        }
    }
}

// ---------------- main: HMMA distance GEMM + argmin + fused gather ----------------
// grid = NRB*2; CTA pair (rb, half) each handles 512 codes of the same 128 rows.
// 512 threads = 16 warps = 4 row-groups x 4 code-groups.
__global__ void __launch_bounds__(512, 1)
vq_mma_kernel(const float* __restrict__ x, const float* __restrict__ embed,
              float* __restrict__ out) {
    extern __shared__ char sm[];
    uint32_t* sA  = (uint32_t*)(sm + SA_OFF);
    float*    sE2 = (float*)(sm + SE2_OFF);
    float*    sRF = (float*)(sm + SRF_OFF);
    int*      sRI = (int*)(sm + SRI_OFF);
    float*    sX  = (float*)(sm + SX_OFF);
    const uint32_t sBaddr = smem_u32(sm + SB_OFF);

    const int tid = threadIdx.x, lane = tid & 31, w = tid >> 5;
    const int rg = w & 3, cg = w >> 2;            // 4 row-groups x 4 code-groups
    const int rb = blockIdx.x >> 1, half = blockIdx.x & 1;
    const int code0 = half * 512;

    // prefetch this half's B chunks 0,1
    {
        const char* src0 = (const char*)g_Bp + (size_t)(half * CPC) * CHB;
        for (int k = tid; k < CHB / 16; k += 512) cp16(sBaddr + k * 16, src0 + k * 16);
        cp_commit();
        const char* src1 = src0 + CHB;
        for (int k = tid; k < CHB / 16; k += 512) cp16(sBaddr + CHB + k * 16, src1 + k * 16);
        cp_commit();
    }

    // build A fragments + fp32 x tile; thread = (row, quarter)
    {
        const int r = tid >> 2, q = tid & 3;
        const int grow = rb * ROWS_CTA + r;
        const float* xp = x + (size_t)(grow >> 11) * (DIM * TT) + (grow & (TT - 1));
        uint32_t h0[8], h1[8];
#pragma unroll
        for (int j = 0; j < 8; ++j) {
            float va = xp[(size_t)(16 * q + 2 * j) * TT];
            float vb = xp[(size_t)(16 * q + 2 * j + 1) * TT];
            sX[r * 64 + 16 * q + 2 * j] = va;
            sX[r * 64 + 16 * q + 2 * j + 1] = vb;
            uint32_t a0, a1, b0, b1;
            split2(va, a0, a1);
            split2(vb, b0, b1);
            h0[j] = a0 | (b0 << 16);
            h1[j] = a1 | (b1 << 16);
        }
        const int mt = r >> 4, rr = r & 15;
        const int wsel = (rr < 8) ? 0 : 1;
#pragma unroll
        for (int sp = 0; sp < 2; ++sp) {
            const int pkt = sp * 4 + q;
            const uint32_t* hp = sp ? h1 : h0;
#pragma unroll
            for (int c = 0; c < 4; ++c) {
                uint32_t* dst = sA + (((mt * 8 + pkt) * 32) + 4 * (rr & 7) + c) * 4 + wsel;
                dst[0] = hp[c];
                dst[2] = hp[4 + c];
            }
        }
        for (int i = tid; i < NUM_E; i += 512) sE2[i] = g_e2[i];
    }
    __syncthreads();

    // logical k-tiles: x0e0 (acc0), x0e1 (acc1), x1e0 (acc1)
    const int PA_[12]  = {0,1,2,3, 0,1,2,3, 4,5,6,7};
    const int PB_[12]  = {0,1,2,3, 4,5,6,7, 0,1,2,3};
    const int ACC_[12] = {0,0,0,0, 1,1,1,1, 1,1,1,1};

    float best[4];
    int   bidx[4];
#pragma unroll
    for (int h = 0; h < 4; ++h) { best[h] = 3.4e38f; bidx[h] = 0; }

    for (int i = 0; i < CPC; ++i) {
        if (i < CPC - 1) asm volatile("cp.async.wait_group 1;" ::: "memory");
        else             asm volatile("cp.async.wait_group 0;" ::: "memory");
        __syncthreads();
        const uint32_t* Bb = (const uint32_t*)(sm + SB_OFF + (i & 1) * CHB);

        float acc[2][2][4][4];   // [set][m][n][j]
#pragma unroll
        for (int s = 0; s < 2; ++s)
#pragma unroll
            for (int m = 0; m < 2; ++m)
#pragma unroll
                for (int n = 0; n < 4; ++n)
#pragma unroll
                    for (int j = 0; j < 4; ++j) acc[s][m][n][j] = 0.f;

#pragma unroll
        for (int lkt = 0; lkt < 12; ++lkt) {
            const int pa = PA_[lkt], pb = PB_[lkt], as = ACC_[lkt];
            uint4 Af[2];
#pragma unroll
            for (int m = 0; m < 2; ++m)
                Af[m] = *(const uint4*)(sA + ((((rg * 2 + m) * 8 + pa) * 32) + lane) * 4);
#pragma unroll
            for (int n = 0; n < 4; ++n) {
                uint2 Bf = *(const uint2*)(Bb + (((pb * 16 + cg * 4 + n) * 32) + lane) * 2);
#pragma unroll
                for (int m = 0; m < 2; ++m) mma16816(acc[as][m][n], Af[m], Bf);
            }
        }
        __syncthreads();   // all warps done reading this B buffer

        if (i + 2 < CPC) {
            const char* src = (const char*)g_Bp + (size_t)(half * CPC + i + 2) * CHB;
            const uint32_t dst = sBaddr + (i & 1) * CHB;
            for (int k = tid; k < CHB / 16; k += 512) cp16(dst + k * 16, src + k * 16);
            cp_commit();
        }

        // epilogue: dot = acc0 + acc1/2048; score = -2*dot + ||e||^2
        const int cb = code0 + i * 128 + cg * 32 + 2 * (lane & 3);
#pragma unroll
        for (int n = 0; n < 4; ++n) {
            const int c0 = cb + n * 8;
            const float ea = sE2[c0], eb = sE2[c0 + 1];
#pragma unroll
            for (int m = 0; m < 2; ++m) {
                const int ha = 2 * m, hb = 2 * m + 1;
                float d0 = fmaf(acc[1][m][n][0], INV2048, acc[0][m][n][0]);
                float d1 = fmaf(acc[1][m][n][1], INV2048, acc[0][m][n][1]);
                float d2 = fmaf(acc[1][m][n][2], INV2048, acc[0][m][n][2]);
                float d3 = fmaf(acc[1][m][n][3], INV2048, acc[0][m][n][3]);
                float s0 = fmaf(-2.f, d0, ea);
                float s1 = fmaf(-2.f, d1, eb);
                float s2 = fmaf(-2.f, d2, ea);
                float s3 = fmaf(-2.f, d3, eb);
                if (s0 < best[ha]) { best[ha] = s0; bidx[ha] = c0; }
                if (s1 < best[ha]) { best[ha] = s1; bidx[ha] = c0 + 1; }
                if (s2 < best[hb]) { best[hb] = s2; bidx[hb] = c0; }
                if (s3 < best[hb]) { best[hb] = s3; bidx[hb] = c0 + 1; }
            }
        }
    }

    // quad reduce (lanes 4q..4q+3 share rows), idx tie-break = smaller
#pragma unroll
    for (int h = 0; h < 4; ++h) {
#pragma unroll
        for (int off = 1; off < 4; off <<= 1) {
            float os = __shfl_xor_sync(0xffffffffu, best[h], off);
            int   oi = __shfl_xor_sync(0xffffffffu, bidx[h], off);
            if (os < best[h] || (os == best[h] && oi < bidx[h])) { best[h] = os; bidx[h] = oi; }
        }
    }
    if ((lane & 3) == 0) {
        const int q = lane >> 2;
#pragma unroll
        for (int h = 0; h < 4; ++h) {
            const int m = h >> 1, hb = h & 1;
            const int row = rg * 32 + m * 16 + hb * 8 + q;
            sRF[row * 4 + cg] = best[h];
            sRI[row * 4 + cg] = bidx[h];
        }
    }
    __syncthreads();

    // per-row merge of 4 code-groups; cross-CTA merge via packed atomicMin
    if (tid < ROWS_CTA) {
        float bv = sRF[tid * 4];
        int   bi = sRI[tid * 4];
#pragma unroll
        for (int g = 1; g < 4; ++g) {
            float v = sRF[tid * 4 + g];
            int   i = sRI[tid * 4 + g];
            if (v < bv || (v == bv && i < bi)) { bv = v; bi = i; }
        }
        const unsigned long long key =
            ((unsigned long long)okey(bv) << 10) | (unsigned long long)bi;
        atomicMin(&g_slot[rb * ROWS_CTA + tid], key);
    }
    __syncthreads();

    // last CTA of the pair does the gather for these rows
    __shared__ int s_last;
    if (tid == 0) {
        __threadfence();
        s_last = (atomicAdd(&g_done[rb], 1) == 1);
    }
    __syncthreads();
    if (!s_last) return;
    __threadfence();   // acquire: partner's atomicMin results visible

    {
        __shared__ float warpsum[16];
        const int r = tid & 127, q = tid >> 7;    // q = dim quarter
        const int grow = rb * ROWS_CTA + r;
        const unsigned long long key =
            *(volatile unsigned long long*)&g_slot[grow];
        const int bi = (int)(key & 1023ull);
        if (q == 0) {
            out[IDX_OFF + grow] = (float)bi;
            atomicAdd(&g_counts[bi], 1);
        }
        const int b_i = grow >> 11, t_i = grow & (TT - 1);
        const float* ep = embed + (size_t)bi * DIM + q * 16;
        const float* xp = sX + r * 64 + q * 16;
        float* op = out + ((size_t)b_i * DIM + q * 16) * TT + t_i;
        float s = 0.f;
#pragma unroll
        for (int j = 0; j < 16; ++j) {
            float e = ep[j];
            float xv = xp[j];
            float d = e - xv;
            op[(size_t)j * TT] = xv + d;   // straight-through: x + (q - x)
            s = fmaf(d, d, s);
        }
#pragma unroll
        for (int o = 16; o; o >>= 1) s += __shfl_down_sync(0xffffffffu, s, o);
        if (lane == 0) warpsum[w] = s;
        __syncthreads();
        if (w == 0) {
            float v = warpsum[lane >> 1] * 0.5f;  // each pair counted once
            v = (lane < 16) ? warpsum[lane] : 0.f;
#pragma unroll
            for (int o = 8; o; o >>= 1) v += __shfl_down_sync(0xffffffffu, v, o);
            if (lane == 0) atomicAdd(&g_sumsq, v);
        }
    }
}

// ---------------- finalize ----------------
__global__ void finalize_kernel(float* __restrict__ out) {
    __shared__ float s1[32], s2[32];
    const int tid = threadIdx.x;
    float p = (float)g_counts[tid] * (1.0f / (float)NROWS);
    out[AVG_OFF + tid] = p;
    float t1 = p * logf(p + 1e-10f);
    float t2 = p * logf(p * (float)NUM_E + 1e-10f);
#pragma unroll
    for (int o = 16; o; o >>= 1) {
        t1 += __shfl_down_sync(0xffffffffu, t1, o);
        t2 += __shfl_down_sync(0xffffffffu, t2, o);
    }
    const int lane = tid & 31, w = tid >> 5;
    if (lane == 0) { s1[w] = t1; s2[w] = t2; }
    __syncthreads();
    if (w == 0) {
        float a = s1[lane], b = s2[lane];
#pragma unroll
        for (int o = 16; o; o >>= 1) {
            a += __shfl_down_sync(0xffffffffu, a, o);
            b += __shfl_down_sync(0xffffffffu, b, o);
        }
        if (lane == 0) {
            out[PERP_OFF]   = expf(-a);
            out[USAGE_OFF]  = b;
            out[COMMIT_OFF] = 0.25f * g_sumsq / (float)NELEM;
        }
    }
}

extern "C" void kernel_launch(void* const* d_in, const int* in_sizes, int n_in,
                              void* d_out, int out_size) {
    const float* x     = (const float*)d_in[0];
    const float* embed = (const float*)d_in[1];
    float* out = (float*)d_out;

    cudaFuncSetAttribute(vq_mma_kernel, cudaFuncAttributeMaxDynamicSharedMemorySize, SMEM_DYN);

    prep_kernel<<<8, 128>>>(embed);
    vq_mma_kernel<<<NRB * 2, 512, SMEM_DYN>>>(x, embed, out);
    finalize_kernel<<<1, 1024>>>(out);
}

// round 7
// speedup vs baseline: 1.8829x; 1.1589x over previous
#include <cuda_runtime.h>
#include <cuda_fp16.h>
#include <cstdint>
#include <math.h>

// ---------------- problem constants ----------------
#define NUM_E 1024
#define DIM   64
#define TT    2048
#define BB    32
#define NROWS (BB * TT)          // 65536
#define NELEM (BB * DIM * TT)    // 4194304

// output layout (flattened tuple, fp32)
#define COMMIT_OFF 4194304
#define PERP_OFF   4194305
#define AVG_OFF    4194306
#define IDX_OFF    4195330
#define USAGE_OFF  4260866

// ---------------- tiling ----------------
#define ROWS_CTA 64                  // rows per CTA (4 m-tiles)
#define NCH      8                   // code chunks of 128
#define CHB      32768               // packed B chunk: 8 pkt * 16 nt * 32 * 8B

// smem offsets
#define SA_OFF   0                   // A frags: 4 mt * 8 pkt * 32 * 16B = 16KB
#define SB_OFF   16384               // B frags: 2 * 32KB
#define SE2_OFF  81920               // 4KB
#define SRF_OFF  86016               // 64*8 floats = 2KB
#define SRI_OFF  88064               // 64*8 ints  = 2KB
#define SMEM_DYN 90112

#define INV2048 4.8828125e-4f

// ---------------- device scratch ----------------
__device__ __align__(16) unsigned char g_Bp[NCH * CHB];  // packed B frags
__device__ float g_e2[NUM_E];
__device__ int   g_idx[NROWS];
__device__ int   g_counts[NUM_E];
__device__ float g_sumsq;

// ---------------- helpers ----------------
__device__ __forceinline__ uint32_t smem_u32(const void* p) {
    uint32_t a;
    asm("{ .reg .u64 t; cvta.to.shared.u64 t, %1; cvt.u32.u64 %0, t; }" : "=r"(a) : "l"(p));
    return a;
}
__device__ __forceinline__ void cp16(uint32_t saddr, const void* g) {
    asm volatile("cp.async.cg.shared.global [%0], [%1], 16;" :: "r"(saddr), "l"(g));
}
__device__ __forceinline__ void cp_commit() {
    asm volatile("cp.async.commit_group;" ::: "memory");
}
__device__ __forceinline__ void mma16816(float* d, const uint4 a, const uint2 b) {
    asm volatile(
        "mma.sync.aligned.m16n8k16.row.col.f32.f16.f16.f32 "
        "{%0,%1,%2,%3}, {%4,%5,%6,%7}, {%8,%9}, {%0,%1,%2,%3};"
        : "+f"(d[0]), "+f"(d[1]), "+f"(d[2]), "+f"(d[3])
        : "r"(a.x), "r"(a.y), "r"(a.z), "r"(a.w), "r"(b.x), "r"(b.y));
}
// scaled 2-split: v = h0 + h1/2048 with error ~2^-33
__device__ __forceinline__ void split2(float v, uint32_t& u0, uint32_t& u1) {
    __half h0 = __float2half_rn(v);
    float f0 = __half2float(h0);
    __half h1 = __float2half_rn((v - f0) * 2048.0f);
    u0 = (uint32_t)__half_as_ushort(h0);
    u1 = (uint32_t)__half_as_ushort(h1);
}

// ---------------- prep: pack codebook frags + norms + zero scratch ----------------
// 32 blocks x 32 threads, one code per thread
__global__ void prep_kernel(const float* __restrict__ embed) {
    const int c = blockIdx.x * 32 + threadIdx.x;
    const float* e = embed + (size_t)c * DIM;
    uint32_t h0[32], h1[32];
    float s = 0.f;
#pragma unroll 8
    for (int j = 0; j < 32; ++j) {
        float2 v = *(const float2*)(e + 2 * j);
        s += v.x * v.x + v.y * v.y;
        uint32_t a0, a1, b0, b1;
        split2(v.x, a0, a1);
        split2(v.y, b0, b1);
        h0[j] = a0 | (b0 << 16);
        h1[j] = a1 | (b1 << 16);
    }
    g_e2[c] = s;
    g_counts[c] = 0;
    if (c == 0) g_sumsq = 0.f;

    const int chunk = c >> 7, n_in = c & 127, nt = n_in >> 3, lq = n_in & 7;
    uint32_t* dstb = (uint32_t*)(g_Bp + (size_t)chunk * CHB);
#pragma unroll
    for (int pkt = 0; pkt < 8; ++pkt) {
        const uint32_t* hp = (pkt < 4) ? h0 : h1;
        const int kb = (pkt & 3) * 8;
#pragma unroll
        for (int cc = 0; cc < 4; ++cc) {
            uint32_t* d = dstb + (((pkt * 16 + nt) * 32) + 4 * lq + cc) * 2;
            d[0] = hp[kb + cc];
            d[1] = hp[kb + 4 + cc];
        }
    }
}

// ---------------- main: HMMA distance GEMM + fused argmin ----------------
// 512 threads = 16 warps = 2 row-groups x 8 code-groups; 64 rows/CTA; 2 CTAs/SM
__global__ void __launch_bounds__(512, 2)
vq_mma_kernel(const float* __restrict__ x, float* __restrict__ out_idxf) {
    extern __shared__ char sm[];
    uint32_t* sA  = (uint32_t*)(sm + SA_OFF);
    float*    sE2 = (float*)(sm + SE2_OFF);
    float*    sRF = (float*)(sm + SRF_OFF);
    int*      sRI = (int*)(sm + SRI_OFF);
    const uint32_t sBaddr = smem_u32(sm + SB_OFF);

    const int tid = threadIdx.x, lane = tid & 31, w = tid >> 5;
    const int rg = w >> 3, cg = w & 7;   // 2 row-groups x 8 code-groups

    // prefetch B chunks 0,1
    {
        const char* src0 = (const char*)g_Bp;
        for (int k = tid; k < CHB / 16; k += 512) cp16(sBaddr + k * 16, src0 + k * 16);
        cp_commit();
        const char* src1 = src0 + CHB;
        for (int k = tid; k < CHB / 16; k += 512) cp16(sBaddr + CHB + k * 16, src1 + k * 16);
        cp_commit();
    }

    // build A fragments: thread = (row, octant); octant o covers dims 8o..8o+7
    {
        const int r = tid >> 3, o = tid & 7;
        const int q = o >> 1, halfq = o & 1;      // quarter, half-of-quarter
        const int grow = blockIdx.x * ROWS_CTA + r;
        const float* xp = x + (size_t)(grow >> 11) * (DIM * TT) + (grow & (TT - 1));
        uint32_t h0[4], h1[4];
#pragma unroll
        for (int j = 0; j < 4; ++j) {
            float va = xp[(size_t)(8 * o + 2 * j) * TT];
            float vb = xp[(size_t)(8 * o + 2 * j + 1) * TT];
            uint32_t a0, a1, b0, b1;
            split2(va, a0, a1);
            split2(vb, b0, b1);
            h0[j] = a0 | (b0 << 16);
            h1[j] = a1 | (b1 << 16);
        }
        const int mt = r >> 4, rr = r & 15;
        const int wsel = ((rr < 8) ? 0 : 1) + (halfq ? 2 : 0);
#pragma unroll
        for (int sp = 0; sp < 2; ++sp) {
            const int pkt = sp * 4 + q;
            const uint32_t* hp = sp ? h1 : h0;
#pragma unroll
            for (int cc = 0; cc < 4; ++cc)
                sA[(((mt * 8 + pkt) * 32) + 4 * (rr & 7) + cc) * 4 + wsel] = hp[cc];
        }
        for (int i = tid; i < NUM_E; i += 512) sE2[i] = g_e2[i];
    }
    __syncthreads();

    float best[4];
    int   bidx[4];
#pragma unroll
    for (int h = 0; h < 4; ++h) { best[h] = 3.4e38f; bidx[h] = 0; }

    for (int ch = 0; ch < NCH; ++ch) {
        if (ch < NCH - 1) asm volatile("cp.async.wait_group 1;" ::: "memory");
        else              asm volatile("cp.async.wait_group 0;" ::: "memory");
        __syncthreads();
        const uint32_t* Bb = (const uint32_t*)(sm + SB_OFF + (ch & 1) * CHB);

        float acc[2][2][4];   // [m][n][j]
#pragma unroll
        for (int m = 0; m < 2; ++m)
#pragma unroll
            for (int n = 0; n < 2; ++n)
#pragma unroll
                for (int j = 0; j < 4; ++j) acc[m][n][j] = 0.f;

        // phase 1: small products x0*e1 (pa=q, pb=4+q) and x1*e0 (pa=4+q, pb=q)
#pragma unroll
        for (int lkt = 0; lkt < 8; ++lkt) {
            const int qq = lkt & 3;
            const int pa = (lkt < 4) ? qq : (4 + qq);
            const int pb = (lkt < 4) ? (4 + qq) : qq;
            uint4 Af[2];
#pragma unroll
            for (int m = 0; m < 2; ++m)
                Af[m] = *(const uint4*)(sA + ((((rg * 2 + m) * 8 + pa) * 32) + lane) * 4);
#pragma unroll
            for (int n = 0; n < 2; ++n) {
                uint2 Bf = *(const uint2*)(Bb + (((pb * 16 + cg * 2 + n) * 32) + lane) * 2);
#pragma unroll
                for (int m = 0; m < 2; ++m) mma16816(acc[m][n], Af[m], Bf);
            }
        }
        // scale small-product sum into final units
#pragma unroll
        for (int m = 0; m < 2; ++m)
#pragma unroll
            for (int n = 0; n < 2; ++n)
#pragma unroll
                for (int j = 0; j < 4; ++j) acc[m][n][j] *= INV2048;

        // phase 2: main product x0*e0 (pa=pb=q)
#pragma unroll
        for (int qq = 0; qq < 4; ++qq) {
            uint4 Af[2];
#pragma unroll
            for (int m = 0; m < 2; ++m)
                Af[m] = *(const uint4*)(sA + ((((rg * 2 + m) * 8 + qq) * 32) + lane) * 4);
#pragma unroll
            for (int n = 0; n < 2; ++n) {
                uint2 Bf = *(const uint2*)(Bb + (((qq * 16 + cg * 2 + n) * 32) + lane) * 2);
#pragma unroll
                for (int m = 0; m < 2; ++m) mma16816(acc[m][n], Af[m], Bf);
            }
        }
        __syncthreads();   // all warps done reading this B buffer

        if (ch + 2 < NCH) {
            const char* src = (const char*)g_Bp + (size_t)(ch + 2) * CHB;
            const uint32_t dst = sBaddr + (ch & 1) * CHB;
            for (int k = tid; k < CHB / 16; k += 512) cp16(dst + k * 16, src + k * 16);
            cp_commit();
        }

        // epilogue: score = -2*dot + ||e||^2 (dot already complete in acc)
        const int cb = ch * 128 + cg * 16 + 2 * (lane & 3);
#pragma unroll
        for (int n = 0; n < 2; ++n) {
            const int c0 = cb + n * 8;
            const float ea = sE2[c0], eb = sE2[c0 + 1];
#pragma unroll
            for (int m = 0; m < 2; ++m) {
                const int ha = 2 * m, hb = 2 * m + 1;
                float s0 = fmaf(-2.f, acc[m][n][0], ea);
                float s1 = fmaf(-2.f, acc[m][n][1], eb);
                float s2 = fmaf(-2.f, acc[m][n][2], ea);
                float s3 = fmaf(-2.f, acc[m][n][3], eb);
                if (s0 < best[ha]) { best[ha] = s0; bidx[ha] = c0; }
                if (s1 < best[ha]) { best[ha] = s1; bidx[ha] = c0 + 1; }
                if (s2 < best[hb]) { best[hb] = s2; bidx[hb] = c0; }
                if (s3 < best[hb]) { best[hb] = s3; bidx[hb] = c0 + 1; }
            }
        }
    }

    // quad reduce (lanes 4q..4q+3 share rows), idx tie-break = smaller
#pragma unroll
    for (int h = 0; h < 4; ++h) {
#pragma unroll
        for (int off = 1; off < 4; off <<= 1) {
            float os = __shfl_xor_sync(0xffffffffu, best[h], off);
            int   oi = __shfl_xor_sync(0xffffffffu, bidx[h], off);
            if (os < best[h] || (os == best[h] && oi < bidx[h])) { best[h] = os; bidx[h] = oi; }
        }
    }
    if ((lane & 3) == 0) {
        const int q = lane >> 2;
#pragma unroll
        for (int h = 0; h < 4; ++h) {
            const int m = h >> 1, hb = h & 1;
            const int row = rg * 32 + m * 16 + hb * 8 + q;
            sRF[row * 8 + cg] = best[h];
            sRI[row * 8 + cg] = bidx[h];
        }
    }
    __syncthreads();
    // merge the eight code-groups per row, write results
    if (tid < ROWS_CTA) {
        float bv = sRF[tid * 8];
        int   bi = sRI[tid * 8];
#pragma unroll
        for (int g = 1; g < 8; ++g) {
            float v = sRF[tid * 8 + g];
            int   i = sRI[tid * 8 + g];
            if (v < bv || (v == bv && i < bi)) { bv = v; bi = i; }
        }
        const int grow = blockIdx.x * ROWS_CTA + tid;
        g_idx[grow] = bi;
        out_idxf[grow] = (float)bi;
        atomicAdd(&g_counts[bi], 1);
    }
}

// ---------------- gather + straight-through + commitment loss ----------------
__global__ void gather_kernel(const float* __restrict__ x,
                              const float* __restrict__ embed,
                              float* __restrict__ out_q) {
    __shared__ float warpsum[8];
    const int gid = blockIdx.x * blockDim.x + threadIdx.x;
    const int lin = gid * 4;
    const int t_i = lin & (TT - 1);
    const int d_i = (lin >> 11) & (DIM - 1);
    const int b_i = lin >> 17;

    float4 xv = *(const float4*)(x + lin);
    const int rowbase = (b_i << 11) + t_i;
    int4 id = *(const int4*)(g_idx + rowbase);

    float q0 = embed[id.x * DIM + d_i];
    float q1 = embed[id.y * DIM + d_i];
    float q2 = embed[id.z * DIM + d_i];
    float q3 = embed[id.w * DIM + d_i];

    float d0 = q0 - xv.x, d1 = q1 - xv.y, d2 = q2 - xv.z, d3 = q3 - xv.w;
    float4 ov = make_float4(xv.x + d0, xv.y + d1, xv.z + d2, xv.w + d3);
    *(float4*)(out_q + lin) = ov;

    float s = d0 * d0 + d1 * d1 + d2 * d2 + d3 * d3;
#pragma unroll
    for (int o = 16; o; o >>= 1) s += __shfl_down_sync(0xffffffffu, s, o);
    const int lane = threadIdx.x & 31, w = threadIdx.x >> 5;
    if (lane == 0) warpsum[w] = s;
    __syncthreads();
    if (w == 0) {
        float v = lane < 8 ? warpsum[lane] : 0.f;
#pragma unroll
        for (int o = 4; o; o >>= 1) v += __shfl_down_sync(0xffffffffu, v, o);
        if (lane == 0) atomicAdd(&g_sumsq, v);
    }
}

// ---------------- finalize ----------------
__global__ void finalize_kernel(float* __restrict__ out) {
    __shared__ float s1[32], s2[32];
    const int tid = threadIdx.x;
    float p = (float)g_counts[tid] * (1.0f / (float)NROWS);
    out[AVG_OFF + tid] = p;
    float t1 = p * logf(p + 1e-10f);
    float t2 = p * logf(p * (float)NUM_E + 1e-10f);
#pragma unroll
    for (int o = 16; o; o >>= 1) {
        t1 += __shfl_down_sync(0xffffffffu, t1, o);
        t2 += __shfl_down_sync(0xffffffffu, t2, o);
    }
    const int lane = tid & 31, w = tid >> 5;
    if (lane == 0) { s1[w] = t1; s2[w] = t2; }
    __syncthreads();
    if (w == 0) {
        float a = s1[lane], b = s2[lane];
#pragma unroll
        for (int o = 16; o; o >>= 1) {
            a += __shfl_down_sync(0xffffffffu, a, o);
            b += __shfl_down_sync(0xffffffffu, b, o);
        }
        if (lane == 0) {
            out[PERP_OFF]   = expf(-a);
            out[USAGE_OFF]  = b;
            out[COMMIT_OFF] = 0.25f * g_sumsq / (float)NELEM;
        }
    }
}

extern "C" void kernel_launch(void* const* d_in, const int* in_sizes, int n_in,
                              void* d_out, int out_size) {
    const float* x     = (const float*)d_in[0];
    const float* embed = (const float*)d_in[1];
    float* out = (float*)d_out;

    cudaFuncSetAttribute(vq_mma_kernel, cudaFuncAttributeMaxDynamicSharedMemorySize, SMEM_DYN);

    prep_kernel<<<32, 32>>>(embed);
    vq_mma_kernel<<<NROWS / ROWS_CTA, 512, SMEM_DYN>>>(x, out + IDX_OFF);
    gather_kernel<<<NELEM / (256 * 4), 256>>>(x, embed, out);
    finalize_kernel<<<1, 1024>>>(out);
}